// round 1
// baseline (speedup 1.0000x reference)
#include <cuda_runtime.h>
#include <cuda_bf16.h>

// Conv2d: x(16,64,112,112) * w(64,64,3,3) + b(64) -> out(16,64,112,112)
// stride 1, pad 1, fp32.
//
// Strategy (R1): implicit GEMM per output row.
//   grid = 16*112 blocks, one per (n, h). Block computes 64(F) x 112(W).
//   K = C*9 = 576 reduction, chunked 8 channels at a time through shared.
//   Each of 128 threads owns an 8F x 7W register tile, held as 4x7
//   f32x2 packed accumulators (F-pairs) driven by fma.rn.f32x2
//   (128 fp32 FMA lanes/SM/cyc vs 64 for scalar FFMA on sm_103a).

#define CIN   64
#define COUT  64
#define H     112
#define W     112
#define NB    16

#define CCHUNK 8            // channels per shared-memory chunk
#define XPITCH 120          // padded row pitch in shared (avoid pathological strides)

// Scratch for weights re-laid-out as [c][k][f] (coalesced shared fills).
__device__ float g_wtr[CIN * 9 * COUT];

__global__ void transpose_weights_kernel(const float* __restrict__ wt) {
    int idx = blockIdx.x * blockDim.x + threadIdx.x;      // 36864 total
    if (idx >= COUT * CIN * 9) return;
    int f = idx / (CIN * 9);
    int rem = idx % (CIN * 9);
    int c = rem / 9;
    int k = rem % 9;
    g_wtr[(c * 9 + k) * COUT + f] = wt[idx];
}

#define FMA_F32X2(d, a, b) \
    asm("fma.rn.f32x2 %0, %1, %2, %3;" : "=l"(d) : "l"(a), "l"(b), "l"(d))

__global__ __launch_bounds__(128, 4)
void conv3x3_row_kernel(const float* __restrict__ x,
                        const float* __restrict__ bias,
                        float* __restrict__ out) {
    const int bx = blockIdx.x;
    const int n = bx / H;
    const int h = bx % H;

    const int tid = threadIdx.x;
    const int fi  = tid >> 4;          // 0..7  -> f0 = fi*8
    const int wi  = tid & 15;          // 0..15 -> w0 = wi*7
    const int f0  = fi * 8;
    const int w0  = wi * 7;

    __shared__ __align__(16) float xs[CCHUNK][3][XPITCH];
    __shared__ __align__(16) float ws[CCHUNK][9][COUT];

    // init accumulators with bias (packed F-pairs)
    unsigned long long acc[4][7];
    #pragma unroll
    for (int p = 0; p < 4; ++p) {
        float blo = bias[f0 + 2 * p];
        float bhi = bias[f0 + 2 * p + 1];
        unsigned long long bb;
        asm("mov.b64 %0, {%1, %2};" : "=l"(bb)
            : "r"(__float_as_uint(blo)), "r"(__float_as_uint(bhi)));
        #pragma unroll
        for (int j = 0; j < 7; ++j) acc[p][j] = bb;
    }

    #pragma unroll 1
    for (int cc = 0; cc < CIN / CCHUNK; ++cc) {
        const int c0 = cc * CCHUNK;
        __syncthreads();   // previous chunk's compute done before overwrite

        // ---- fill input rows: 8c x 3rows x 114 cols (col = gw+1) ----
        for (int i = tid; i < CCHUNK * 3 * 114; i += 128) {
            int c   = i / (3 * 114);
            int rem = i % (3 * 114);
            int r   = rem / 114;
            int w   = rem % 114;
            int gh  = h - 1 + r;
            int gw  = w - 1;
            float v = 0.0f;
            if ((unsigned)gh < H && (unsigned)gw < W)
                v = x[(((n * CIN) + (c0 + c)) * H + gh) * W + gw];
            xs[c][r][w] = v;
        }
        // ---- fill weights chunk (coalesced from transposed scratch) ----
        for (int i = tid; i < CCHUNK * 9 * COUT; i += 128) {
            // i = ((c*9)+k)*64 + f, matches g_wtr layout offset by c0
            ((float*)ws)[i] = g_wtr[c0 * 9 * COUT + i];
        }
        __syncthreads();

        #pragma unroll 1
        for (int c = 0; c < CCHUNK; ++c) {
            #pragma unroll
            for (int r = 0; r < 3; ++r) {
                // 9 input values cover outputs w0..w0+6 for kw=0..2
                unsigned long long b2[9];
                #pragma unroll
                for (int j = 0; j < 9; ++j) {
                    float bv = xs[c][r][w0 + j];
                    asm("mov.b64 %0, {%1, %1};" : "=l"(b2[j])
                        : "r"(__float_as_uint(bv)));
                }
                #pragma unroll
                for (int kw = 0; kw < 3; ++kw) {
                    const ulonglong2* ap =
                        reinterpret_cast<const ulonglong2*>(&ws[c][r * 3 + kw][f0]);
                    ulonglong2 alo = ap[0];
                    ulonglong2 ahi = ap[1];
                    unsigned long long a2[4] = {alo.x, alo.y, ahi.x, ahi.y};
                    #pragma unroll
                    for (int p = 0; p < 4; ++p)
                        #pragma unroll
                        for (int j = 0; j < 7; ++j)
                            FMA_F32X2(acc[p][j], a2[p], b2[j + kw]);
                }
            }
        }
    }

    // ---- store ----
    #pragma unroll
    for (int p = 0; p < 4; ++p) {
        float* row0 = out + (((n * COUT) + (f0 + 2 * p)) * H + h) * W + w0;
        float* row1 = row0 + H * W;
        #pragma unroll
        for (int j = 0; j < 7; ++j) {
            union { unsigned long long u; float2 f2; } cv;
            cv.u = acc[p][j];
            row0[j] = cv.f2.x;
            row1[j] = cv.f2.y;
        }
    }
}

extern "C" void kernel_launch(void* const* d_in, const int* in_sizes, int n_in,
                              void* d_out, int out_size) {
    const float* x    = (const float*)d_in[0];
    const float* wt   = (const float*)d_in[1];
    const float* bias = (const float*)d_in[2];
    float* out = (float*)d_out;

    transpose_weights_kernel<<<(COUT * CIN * 9 + 255) / 256, 256>>>(wt);
    conv3x3_row_kernel<<<NB * H, 128>>>(x, bias, out);
}

// round 3
// speedup vs baseline: 1.4948x; 1.4948x over previous
#include <cuda_runtime.h>
#include <cstdint>

// Conv2d 3x3 s1 p1: x(16,64,112,112) fp32, w(64,64,3,3), b(64) -> out(16,64,112,112)
//
// R3: warp-level TF32 mma.sync.m16n8k8 implicit GEMM (arch-portable; tcgen05
// PTX is rejected because harness PTX targets compute_103 without 'a').
// One CTA per (n,h): M=128 pixels (112 used), N=64 filters, K=64c*9tap=576.
// kw taps are +-1 shifts of the A shared-memory address; single accumulator.

#define CIN  64
#define COUT 64
#define HH   112
#define WW   112
#define NB   16

#define XP   132               // xs row pitch (floats)
#define CST  (3*XP)            // xs per-channel stride = 396
#define XS_ELEMS (16*CST)      // 6336
#define WS_ELEMS (9*16*64)     // 9216
#define SMEM_BYTES ((XS_ELEMS + WS_ELEMS) * 4)   // 62208
#define OPITCH 73              // sOut pitch

__device__ __forceinline__ uint32_t f2tf32(float v) {
    uint32_t t; asm("cvt.rna.tf32.f32 %0, %1;" : "=r"(t) : "f"(v)); return t;
}

// prepped weights, tf32 bits, layout [kk=kh*3+kw][c=0..63][f=0..63]
__device__ uint32_t g_wt[9 * 64 * 64];

__global__ void prep_weights(const float* __restrict__ wt) {
    int idx = blockIdx.x * blockDim.x + threadIdx.x;
    if (idx >= 9 * 64 * 64) return;
    int kk = idx >> 12;
    int c  = (idx >> 6) & 63;
    int f  = idx & 63;
    g_wt[idx] = f2tf32(wt[(f * 64 + c) * 9 + kk]);
}

#define MMA8(d, a0,a1,a2,a3, b0,b1)                                        \
    asm volatile("mma.sync.aligned.m16n8k8.row.col.f32.tf32.tf32.f32 "     \
        "{%0,%1,%2,%3}, {%4,%5,%6,%7}, {%8,%9}, {%0,%1,%2,%3};"            \
        : "+f"(d[0]), "+f"(d[1]), "+f"(d[2]), "+f"(d[3])                   \
        : "r"(a0), "r"(a1), "r"(a2), "r"(a3), "r"(b0), "r"(b1))

__global__ __launch_bounds__(128, 3)
void conv_mma_kernel(const float* __restrict__ x,
                     const float* __restrict__ bias,
                     float* __restrict__ out) {
    extern __shared__ uint32_t sm[];
    uint32_t* xs = sm;               // 6336: [c16][r3][j132]
    uint32_t* ws = sm + XS_ELEMS;    // 9216: [kk9][c16][f64 xor-swizzled]

    const int tid  = threadIdx.x;
    const int lane = tid & 31;
    const int wid  = tid >> 5;
    const int qv   = lane >> 2;      // groupID 0..7
    const int kv   = lane & 3;       // thread-in-group 0..3
    const int u0   = wid * 32;
    const int xorc = kv << 3;

    const int n = blockIdx.x / HH;
    const int h = blockIdx.x % HH;

    float acc[2][8][4];
    #pragma unroll
    for (int t = 0; t < 2; ++t)
        #pragma unroll
        for (int j = 0; j < 8; ++j)
            #pragma unroll
            for (int r = 0; r < 4; ++r) acc[t][j][r] = 0.f;

    #pragma unroll 1
    for (int ch = 0; ch < 4; ++ch) {
        __syncthreads();    // previous chunk compute done before refill

        // ---- fill xs: 16 channels x 3 rows x 132 (tf32 bits, zero-padded) ----
        const float* xb = x + (size_t)(n * CIN + ch * 16) * (HH * WW);
        for (int i = tid; i < XS_ELEMS; i += 128) {
            int c   = i / CST;
            int rem = i - c * CST;
            int r   = rem / XP;
            int j   = rem - r * XP;
            int gh  = h + r - 1;
            int gw  = j - 1;
            float v = 0.f;
            if ((unsigned)gh < HH && (unsigned)gw < WW)
                v = xb[(size_t)c * (HH * WW) + gh * WW + gw];
            xs[i] = f2tf32(v);
        }
        // ---- fill ws: coalesced read, xor-swizzled shared write ----
        const int gbase = ch * 16 * 64;
        for (int i = tid; i < WS_ELEMS; i += 128) {
            int kk = i >> 10;
            int c  = (i >> 6) & 15;
            int f  = i & 63;
            ws[(kk << 10) + (c << 6) + (f ^ ((c & 3) << 3))] =
                g_wt[(kk << 12) + gbase + (c << 6) + f];
        }
        __syncthreads();

        // ---- 18 k8-steps: s(2 ch-halves) x kh(3) x kw(3) ----
        #pragma unroll
        for (int s = 0; s < 2; ++s) {
            #pragma unroll
            for (int kh = 0; kh < 3; ++kh) {
                const int abase = ((s * 8 + kv) * 3 + kh) * XP + u0 + qv;
                #pragma unroll
                for (int kw = 0; kw < 3; ++kw) {
                    const int ai = abase + kw;
                    uint32_t a0 = xs[ai];
                    uint32_t a1 = xs[ai + 8];
                    uint32_t a2 = xs[ai + 4 * CST];
                    uint32_t a3 = xs[ai + 4 * CST + 8];
                    uint32_t a4 = xs[ai + 16];
                    uint32_t a5 = xs[ai + 24];
                    uint32_t a6 = xs[ai + 4 * CST + 16];
                    uint32_t a7 = xs[ai + 4 * CST + 24];
                    const int kk = kh * 3 + kw;
                    const int bbase = ((kk << 4) + (s << 3) + kv) << 6;
                    #pragma unroll
                    for (int j = 0; j < 8; ++j) {
                        const int bo = bbase + (((j << 3) ^ xorc) + qv);
                        uint32_t b0 = ws[bo];
                        uint32_t b1 = ws[bo + 256];
                        MMA8(acc[0][j], a0, a1, a2, a3, b0, b1);
                        MMA8(acc[1][j], a4, a5, a6, a7, b0, b1);
                    }
                }
            }
        }
    }

    __syncthreads();
    // ---- epilogue: frags -> sOut[u][f] (pitch 73), then coalesced store ----
    float* sOut = (float*)sm;        // 128 x 73 floats = 37376 B (aliases xs/ws)
    #pragma unroll
    for (int t = 0; t < 2; ++t) {
        const int u = u0 + t * 16 + qv;
        #pragma unroll
        for (int j = 0; j < 8; ++j) {
            const int f = j * 8 + kv * 2;
            sOut[u * OPITCH + f]           = acc[t][j][0];
            sOut[u * OPITCH + f + 1]       = acc[t][j][1];
            sOut[(u + 8) * OPITCH + f]     = acc[t][j][2];
            sOut[(u + 8) * OPITCH + f + 1] = acc[t][j][3];
        }
    }
    __syncthreads();

    float* obase = out + ((size_t)(n * COUT) * HH + h) * WW;
    for (int i = tid; i < COUT * WW; i += 128) {
        int f = i / WW;
        int w = i - f * WW;
        obase[(size_t)f * (HH * WW) + w] = sOut[w * OPITCH + f] + __ldg(&bias[f]);
    }
}

extern "C" void kernel_launch(void* const* d_in, const int* in_sizes, int n_in,
                              void* d_out, int out_size) {
    const float* x    = (const float*)d_in[0];
    const float* wt   = (const float*)d_in[1];
    const float* bias = (const float*)d_in[2];
    float* out = (float*)d_out;

    cudaFuncSetAttribute(conv_mma_kernel,
                         cudaFuncAttributeMaxDynamicSharedMemorySize, SMEM_BYTES);
    prep_weights<<<(9 * 64 * 64 + 255) / 256, 256>>>(wt);
    conv_mma_kernel<<<NB * HH, 128, SMEM_BYTES>>>(x, bias, out);
}

// round 4
// speedup vs baseline: 3.1144x; 2.0835x over previous
#include <cuda_runtime.h>
#include <cuda_fp16.h>
#include <cstdint>

// Conv2d 3x3 s1 p1: x(16,64,112,112) fp32, w(64,64,3,3), b(64) -> out(16,64,112,112)
//
// R4: fp16 mma.sync.m16n8k16 implicit GEMM (fp16 mantissa == tf32 mantissa, so
// accuracy matches R3's tf32 path). One CTA per (n,h): M=128 pixels, N=64
// filters, K=576. Channel pairs packed in fp16x2; cp-permuted + u-swizzled
// shared layout makes every A/B fragment fetch one conflict-free LDS.64.

#define CIN  64
#define COUT 64
#define HH   112
#define WW   112
#define NB   16

#define XP   132
#define XS_WORDS (3 * XP * 8)      // 3168 u32 (3 rows x 132 u x 8 cpair slots)
#define WS_WORDS (9 * 64 * 8)      // 4608 u32 (9 taps x 64 f x 8 cpair slots)
#define OPITCH 65
#define SMEM_BYTES (128 * OPITCH * 4)   // 33280 >= (XS_WORDS+WS_WORDS)*4

// prepped weights: [chunk4][kk9][f64][cp'8] fp16x2 (cp' = 2*(cp&3) + (cp>>2))
__device__ uint32_t g_wt16[4 * WS_WORDS];

__global__ void prep_weights(const float* __restrict__ wt) {
    int idx = blockIdx.x * blockDim.x + threadIdx.x;
    if (idx >= 4 * WS_WORDS) return;
    int ch  = idx / WS_WORDS;
    int rem = idx % WS_WORDS;
    int kk  = rem >> 9;
    int f   = (rem >> 3) & 63;
    int cpp = rem & 7;
    int cp  = (cpp >> 1) + ((cpp & 1) << 2);   // invert permutation
    int c0  = ch * 16 + 2 * cp;
    float w0 = wt[(f * CIN + c0) * 9 + kk];
    float w1 = wt[(f * CIN + c0 + 1) * 9 + kk];
    __half2 hv = __floats2half2_rn(w0, w1);
    g_wt16[idx] = *(uint32_t*)&hv;
}

#define MMA16(d, a0, a1, a2, a3, b0, b1)                                     \
    asm volatile("mma.sync.aligned.m16n8k16.row.col.f32.f16.f16.f32 "        \
        "{%0,%1,%2,%3}, {%4,%5,%6,%7}, {%8,%9}, {%0,%1,%2,%3};"              \
        : "+f"(d[0]), "+f"(d[1]), "+f"(d[2]), "+f"(d[3])                     \
        : "r"(a0), "r"(a1), "r"(a2), "r"(a3), "r"(b0), "r"(b1))

__global__ __launch_bounds__(128, 4)
void conv_mma_kernel(const float* __restrict__ x,
                     const float* __restrict__ bias,
                     float* __restrict__ out) {
    extern __shared__ uint32_t sm[];
    uint32_t* xs = sm;                    // XS_WORDS
    uint32_t* ws = sm + XS_WORDS;         // WS_WORDS

    const int tid  = threadIdx.x;
    const int lane = tid & 31;
    const int wid  = tid >> 5;
    const int qv   = lane >> 2;           // groupID 0..7
    const int kv   = lane & 3;            // thread-in-group 0..3
    const int u0   = wid * 32;

    const int n = blockIdx.x / HH;
    const int h = blockIdx.x % HH;

    float acc[2][8][4];
    #pragma unroll
    for (int t = 0; t < 2; ++t)
        #pragma unroll
        for (int j = 0; j < 8; ++j)
            #pragma unroll
            for (int r = 0; r < 4; ++r) acc[t][j][r] = 0.f;

    #pragma unroll 1
    for (int ch = 0; ch < 4; ++ch) {
        __syncthreads();   // previous chunk's compute done before refill

        // ---- xs fill: u fastest (coalesced), swizzled fp16x2 stores ----
        const float* xb = x + (size_t)(n * CIN + ch * 16) * (HH * WW);
        for (int i = tid; i < XS_WORDS; i += 128) {
            int u  = i % XP;
            int rc = i / XP;
            int cp = rc & 7;
            int r  = rc >> 3;
            int gh = h + r - 1;
            int gw = u - 1;
            uint32_t v = 0;
            if ((unsigned)gh < HH && (unsigned)gw < WW) {
                const float* p = xb + (size_t)(2 * cp) * (HH * WW) + gh * WW + gw;
                __half2 hv = __floats2half2_rn(p[0], p[HH * WW]);
                v = *(uint32_t*)&hv;
            }
            int slot = ((2 * (cp & 3)) | (cp >> 2)) ^ ((((u >> 3) & 3) << 1) ^ (u & 4));
            xs[(r * XP + u) * 8 + slot] = v;
        }
        // ---- ws fill: flat coalesced copy (layout prepped in prologue) ----
        for (int i = tid; i < WS_WORDS; i += 128)
            ws[i] = g_wt16[ch * WS_WORDS + i];
        __syncthreads();

        const unsigned long long* xs64 = (const unsigned long long*)xs;
        const unsigned long long* ws64 = (const unsigned long long*)ws;

        // ---- 9 k16-steps (kh x kw), 16 channels each ----
        #pragma unroll
        for (int kh = 0; kh < 3; ++kh) {
            #pragma unroll
            for (int kw = 0; kw < 3; ++kw) {
                const int kk = kh * 3 + kw;
                uint32_t A[2][4];
                #pragma unroll
                for (int t = 0; t < 2; ++t) {
                    int u  = u0 + 16 * t + qv + kw;
                    int e2 = ((u >> 3) & 3) ^ ((u & 4) >> 1);
                    unsigned long long va =
                        xs64[(kh * XP + u) * 4 + (kv ^ e2)];
                    int u2  = u + 8;
                    int e2b = ((u2 >> 3) & 3) ^ ((u2 & 4) >> 1);
                    unsigned long long vb =
                        xs64[(kh * XP + u2) * 4 + (kv ^ e2b)];
                    A[t][0] = (uint32_t)va;          // a0 (k 2kv..2kv+1)
                    A[t][2] = (uint32_t)(va >> 32);  // a2 (k 2kv+8..)
                    A[t][1] = (uint32_t)vb;          // a1 (row +8)
                    A[t][3] = (uint32_t)(vb >> 32);  // a3
                }
                #pragma unroll
                for (int j = 0; j < 8; ++j) {
                    unsigned long long bv =
                        ws64[(kk * 64 + j * 8 + qv) * 4 + kv];
                    uint32_t b0 = (uint32_t)bv;
                    uint32_t b1 = (uint32_t)(bv >> 32);
                    MMA16(acc[0][j], A[0][0], A[0][1], A[0][2], A[0][3], b0, b1);
                    MMA16(acc[1][j], A[1][0], A[1][1], A[1][2], A[1][3], b0, b1);
                }
            }
        }
    }

    __syncthreads();
    // ---- epilogue: frags -> sOut[u][f] (pitch 65), then coalesced store ----
    float* sOut = (float*)sm;     // 128 x 65 floats = 33280 B (aliases xs/ws)
    #pragma unroll
    for (int t = 0; t < 2; ++t) {
        const int u = u0 + t * 16 + qv;
        #pragma unroll
        for (int j = 0; j < 8; ++j) {
            const int f = j * 8 + kv * 2;
            sOut[u * OPITCH + f]           = acc[t][j][0];
            sOut[u * OPITCH + f + 1]       = acc[t][j][1];
            sOut[(u + 8) * OPITCH + f]     = acc[t][j][2];
            sOut[(u + 8) * OPITCH + f + 1] = acc[t][j][3];
        }
    }
    __syncthreads();

    float* obase = out + ((size_t)(n * COUT) * HH + h) * WW;
    for (int i = tid; i < COUT * WW; i += 128) {
        int f = i / WW;
        int w = i - f * WW;
        obase[(size_t)f * (HH * WW) + w] = sOut[w * OPITCH + f] + __ldg(&bias[f]);
    }
}

extern "C" void kernel_launch(void* const* d_in, const int* in_sizes, int n_in,
                              void* d_out, int out_size) {
    const float* x    = (const float*)d_in[0];
    const float* wt   = (const float*)d_in[1];
    const float* bias = (const float*)d_in[2];
    float* out = (float*)d_out;

    cudaFuncSetAttribute(conv_mma_kernel,
                         cudaFuncAttributeMaxDynamicSharedMemorySize, SMEM_BYTES);
    prep_weights<<<(4 * WS_WORDS + 255) / 256, 256>>>(wt);
    conv_mma_kernel<<<NB * HH, 128, SMEM_BYTES>>>(x, bias, out);
}

// round 5
// speedup vs baseline: 3.7638x; 1.2085x over previous
#include <cuda_runtime.h>
#include <cuda_fp16.h>
#include <cstdint>

// Conv2d 3x3 s1 p1: x(16,64,112,112) fp32, w(64,64,3,3), b(64) -> out(16,64,112,112)
//
// R5: fp16 m16n8k16 implicit GEMM, row-blocked (2 output rows / CTA),
// pre-converted + pre-padded fp16 input (prep_x), direct fragment epilogue.

#define CIN  64
#define COUT 64
#define HH   112
#define WW   112
#define NB   16
#define HW   (HH*WW)

#define XP       132                    // u pitch (A reads u up to 129)
#define XROWS    114                    // padded rows: gh = -1..112
#define XS_WORDS (4 * XP * 8)           // 4224 u32: [rr4][u132][slot8]
#define WS_WORDS (9 * 64 * 8)           // 4608 u32
#define SMEM_BYTES ((XS_WORDS + WS_WORDS) * 4)   // 35328

// padded fp16x2 input: [n16][cpair32][row114][u132]
__device__ uint32_t g_x16[(size_t)NB * 32 * XROWS * XP];
// prepped weights: [chunk4][kk9][f64][cp'8] fp16x2
__device__ uint32_t g_wt16[4 * WS_WORDS];

__global__ void prep_weights(const float* __restrict__ wt) {
    int idx = blockIdx.x * blockDim.x + threadIdx.x;
    if (idx >= 4 * WS_WORDS) return;
    int ch  = idx / WS_WORDS;
    int rem = idx % WS_WORDS;
    int kk  = rem >> 9;
    int f   = (rem >> 3) & 63;
    int cpp = rem & 7;
    int cp  = (cpp >> 1) + ((cpp & 1) << 2);
    int c0  = ch * 16 + 2 * cp;
    __half2 hv = __floats2half2_rn(wt[(f * CIN + c0) * 9 + kk],
                                   wt[(f * CIN + c0 + 1) * 9 + kk]);
    g_wt16[idx] = *(uint32_t*)&hv;
}

__global__ void prep_x(const float* __restrict__ x) {
    size_t idx = (size_t)blockIdx.x * blockDim.x + threadIdx.x;
    if (idx >= (size_t)NB * 32 * XROWS * XP) return;
    int u   = idx % XP;
    size_t t1 = idx / XP;
    int row = t1 % XROWS;
    size_t t2 = t1 / XROWS;
    int cpg = t2 % 32;
    int n   = t2 / 32;
    int gh = row - 1, gw = u - 1;
    uint32_t v = 0;
    if ((unsigned)gh < HH && (unsigned)gw < WW) {
        const float* p = x + ((size_t)(n * CIN + 2 * cpg) * HH + gh) * WW + gw;
        __half2 hv = __floats2half2_rn(p[0], p[HW]);
        v = *(uint32_t*)&hv;
    }
    g_x16[idx] = v;
}

#define MMA16(d, a0, a1, a2, a3, b0, b1)                                     \
    asm volatile("mma.sync.aligned.m16n8k16.row.col.f32.f16.f16.f32 "        \
        "{%0,%1,%2,%3}, {%4,%5,%6,%7}, {%8,%9}, {%0,%1,%2,%3};"              \
        : "+f"(d[0]), "+f"(d[1]), "+f"(d[2]), "+f"(d[3])                     \
        : "r"(a0), "r"(a1), "r"(a2), "r"(a3), "r"(b0), "r"(b1))

__global__ __launch_bounds__(256, 2)
void conv_mma_kernel(const float* __restrict__ bias,
                     float* __restrict__ out) {
    extern __shared__ uint32_t sm[];
    uint32_t* xs = sm;                    // XS_WORDS
    uint32_t* ws = sm + XS_WORDS;         // WS_WORDS

    const int tid  = threadIdx.x;
    const int lane = tid & 31;
    const int wid  = tid >> 5;            // 0..7
    const int qv   = lane >> 2;
    const int kv   = lane & 3;
    const int hpr  = wid >> 2;            // 0..1 : output row within pair
    const int u0   = (wid & 3) * 32;

    const int n  = blockIdx.x / 56;
    const int h0 = (blockIdx.x % 56) * 2;

    // bias in regs
    float bj0[8], bj1[8];
    #pragma unroll
    for (int j = 0; j < 8; ++j) {
        bj0[j] = __ldg(bias + j * 8 + kv * 2);
        bj1[j] = __ldg(bias + j * 8 + kv * 2 + 1);
    }

    float acc[2][8][4];
    #pragma unroll
    for (int t = 0; t < 2; ++t)
        #pragma unroll
        for (int j = 0; j < 8; ++j)
            #pragma unroll
            for (int r = 0; r < 4; ++r) acc[t][j][r] = 0.f;

    // fill-role constants: thread -> (rr, cp, u-lane)
    const int fp   = tid >> 3;            // 0..31 : (rr, cp)
    const int fsub = tid & 7;
    const int frr  = fp >> 3;             // 0..3
    const int fcp  = fp & 7;              // 0..7
    const int sperm = (2 * (fcp & 3)) | (fcp >> 2);

    #pragma unroll 1
    for (int ch = 0; ch < 4; ++ch) {
        __syncthreads();   // previous chunk's compute done before refill

        // ---- xs fill: branch-free copy from padded fp16 scratch ----
        const uint32_t* src = g_x16 +
            ((size_t)(n * 32 + ch * 8 + fcp) * XROWS + (h0 + frr)) * XP;
        uint32_t* dst = xs + frr * XP * 8;
        #pragma unroll
        for (int u = fsub; u < XP; u += 8) {
            int e = ((((u >> 3) & 3) << 1) ^ (u & 4));
            dst[u * 8 + (sperm ^ e)] = src[u];
        }
        // ---- ws fill: flat copy ----
        for (int i = tid; i < WS_WORDS; i += 256)
            ws[i] = g_wt16[ch * WS_WORDS + i];
        __syncthreads();

        const unsigned long long* xs64 = (const unsigned long long*)xs;
        const unsigned long long* ws64 = (const unsigned long long*)ws;

        #pragma unroll
        for (int kh = 0; kh < 3; ++kh) {
            const int arow = hpr + kh;       // row in 4-row window
            #pragma unroll
            for (int kw = 0; kw < 3; ++kw) {
                const int kk = kh * 3 + kw;
                uint32_t A[2][4];
                #pragma unroll
                for (int t = 0; t < 2; ++t) {
                    int u  = u0 + 16 * t + qv + kw;
                    int e2 = ((u >> 3) & 3) ^ ((u & 4) >> 1);
                    unsigned long long va = xs64[(arow * XP + u) * 4 + (kv ^ e2)];
                    int u2  = u + 8;
                    int e2b = ((u2 >> 3) & 3) ^ ((u2 & 4) >> 1);
                    unsigned long long vb = xs64[(arow * XP + u2) * 4 + (kv ^ e2b)];
                    A[t][0] = (uint32_t)va;
                    A[t][2] = (uint32_t)(va >> 32);
                    A[t][1] = (uint32_t)vb;
                    A[t][3] = (uint32_t)(vb >> 32);
                }
                #pragma unroll
                for (int j = 0; j < 8; ++j) {
                    unsigned long long bv = ws64[(kk * 64 + j * 8 + qv) * 4 + kv];
                    uint32_t b0 = (uint32_t)bv;
                    uint32_t b1 = (uint32_t)(bv >> 32);
                    MMA16(acc[0][j], A[0][0], A[0][1], A[0][2], A[0][3], b0, b1);
                    MMA16(acc[1][j], A[1][0], A[1][1], A[1][2], A[1][3], b0, b1);
                }
            }
        }
    }

    // ---- direct epilogue: fragments + bias -> global ----
    const int hh = h0 + hpr;
    #pragma unroll
    for (int t = 0; t < 2; ++t) {
        const int ub = u0 + 16 * t + qv;
        #pragma unroll
        for (int j = 0; j < 8; ++j) {
            const int f0 = j * 8 + kv * 2;
            float* o0 = out + ((size_t)(n * COUT + f0) * HH + hh) * WW;
            if (ub < WW) {
                o0[ub]      = acc[t][j][0] + bj0[j];
                o0[HW + ub] = acc[t][j][1] + bj1[j];
            }
            if (ub + 8 < WW) {
                o0[ub + 8]      = acc[t][j][2] + bj0[j];
                o0[HW + ub + 8] = acc[t][j][3] + bj1[j];
            }
        }
    }
}

extern "C" void kernel_launch(void* const* d_in, const int* in_sizes, int n_in,
                              void* d_out, int out_size) {
    const float* x    = (const float*)d_in[0];
    const float* wt   = (const float*)d_in[1];
    const float* bias = (const float*)d_in[2];
    float* out = (float*)d_out;

    cudaFuncSetAttribute(conv_mma_kernel,
                         cudaFuncAttributeMaxDynamicSharedMemorySize, SMEM_BYTES);
    prep_weights<<<(4 * WS_WORDS + 255) / 256, 256>>>(wt);
    size_t nx = (size_t)NB * 32 * XROWS * XP;
    prep_x<<<(unsigned)((nx + 255) / 256), 256>>>(x);
    conv_mma_kernel<<<NB * 56, 256, SMEM_BYTES>>>(bias, out);
}

// round 6
// speedup vs baseline: 4.1214x; 1.0950x over previous
#include <cuda_runtime.h>
#include <cuda_fp16.h>
#include <cstdint>

// Conv2d 3x3 s1 p1: x(16,64,112,112) fp32, w(64,64,3,3), b(64) -> out(16,64,112,112)
//
// R6: fp16 m16n8k16 implicit GEMM, 2 output rows/CTA, cp.async double-buffered
// pipeline. Input pre-converted into the EXACT swizzled shared layout
// ([n][chunk][paddedrow][u][slot] fp16x2) so per-chunk fills are contiguous
// 16B cp.async copies fully overlapped with MMA compute.

#define CIN  64
#define COUT 64
#define HH   112
#define WW   112
#define NB   16
#define HW   (HH*WW)

#define XP       132
#define XROWS    114
#define XS_WORDS (4 * XP * 8)           // 4224 u32 per chunk-tile (4 rows)
#define WS_WORDS (9 * 64 * 8)           // 4608 u32 per chunk
#define BUF_WORDS (XS_WORDS + WS_WORDS) // 8832
#define SMEM_BYTES (2 * BUF_WORDS * 4)  // 70656

// baked input: [n][chunk4][row114][u132][slot8] fp16x2, swizzle pre-applied
__device__ uint32_t g_x16[(size_t)NB * 4 * XROWS * XP * 8];
// prepped weights: [chunk4][kk9][f64][cp'8] fp16x2
__device__ uint32_t g_wt16[4 * WS_WORDS];

__global__ void prep_weights(const float* __restrict__ wt) {
    int idx = blockIdx.x * blockDim.x + threadIdx.x;
    if (idx >= 4 * WS_WORDS) return;
    int ch  = idx / WS_WORDS;
    int rem = idx % WS_WORDS;
    int kk  = rem >> 9;
    int f   = (rem >> 3) & 63;
    int cpp = rem & 7;
    int cp  = (cpp >> 1) + ((cpp & 1) << 2);
    int c0  = ch * 16 + 2 * cp;
    __half2 hv = __floats2half2_rn(wt[(f * CIN + c0) * 9 + kk],
                                   wt[(f * CIN + c0 + 1) * 9 + kk]);
    g_wt16[idx] = *(uint32_t*)&hv;
}

__global__ void prep_x(const float* __restrict__ x) {
    size_t idx = (size_t)blockIdx.x * blockDim.x + threadIdx.x;
    if (idx >= (size_t)NB * 4 * XROWS * XP * 8) return;
    int slot = idx & 7;
    size_t t  = idx >> 3;
    int u    = t % XP;
    size_t t2 = t / XP;
    int row  = t2 % XROWS;
    size_t t3 = t2 / XROWS;
    int ch   = t3 & 3;
    int n    = t3 >> 2;

    int e  = ((((u >> 3) & 3) << 1) ^ (u & 4));
    int s2 = slot ^ e;
    int cp = (s2 >> 1) | ((s2 & 1) << 2);
    int c0 = ch * 16 + 2 * cp;

    int gh = row - 1, gw = u - 1;
    uint32_t v = 0;
    if ((unsigned)gh < HH && (unsigned)gw < WW) {
        const float* p = x + ((size_t)(n * CIN + c0) * HH + gh) * WW + gw;
        __half2 hv = __floats2half2_rn(p[0], p[HW]);
        v = *(uint32_t*)&hv;
    }
    g_x16[idx] = v;
}

#define MMA16(d, a0, a1, a2, a3, b0, b1)                                     \
    asm volatile("mma.sync.aligned.m16n8k16.row.col.f32.f16.f16.f32 "        \
        "{%0,%1,%2,%3}, {%4,%5,%6,%7}, {%8,%9}, {%0,%1,%2,%3};"              \
        : "+f"(d[0]), "+f"(d[1]), "+f"(d[2]), "+f"(d[3])                     \
        : "r"(a0), "r"(a1), "r"(a2), "r"(a3), "r"(b0), "r"(b1))

__device__ __forceinline__ void cp16(uint32_t dst, const void* src) {
    asm volatile("cp.async.ca.shared.global [%0], [%1], 16;"
                 :: "r"(dst), "l"(src));
}

__global__ __launch_bounds__(256, 2)
void conv_mma_kernel(const float* __restrict__ bias,
                     float* __restrict__ out) {
    extern __shared__ uint32_t sm[];
    const uint32_t sbase = (uint32_t)__cvta_generic_to_shared(sm);

    const int tid  = threadIdx.x;
    const int lane = tid & 31;
    const int wid  = tid >> 5;
    const int qv   = lane >> 2;
    const int kv   = lane & 3;
    const int hpr  = wid >> 2;
    const int u0   = (wid & 3) * 32;

    const int n  = blockIdx.x / 56;
    const int h0 = (blockIdx.x % 56) * 2;

    float bj0[8], bj1[8];
    #pragma unroll
    for (int j = 0; j < 8; ++j) {
        bj0[j] = __ldg(bias + j * 8 + kv * 2);
        bj1[j] = __ldg(bias + j * 8 + kv * 2 + 1);
    }

    float acc[2][8][4];
    #pragma unroll
    for (int t = 0; t < 2; ++t)
        #pragma unroll
        for (int j = 0; j < 8; ++j)
            #pragma unroll
            for (int r = 0; r < 4; ++r) acc[t][j][r] = 0.f;

    // ---- async fill of one chunk into buffer b ----
    auto fill = [&](int ch, int b) {
        const uint4* xsrc = (const uint4*)(g_x16 +
            (((size_t)(n * 4 + ch) * XROWS + h0) * (XP * 8)));
        const uint4* wsrc = (const uint4*)(g_wt16 + ch * WS_WORDS);
        uint32_t xdst = sbase + b * (BUF_WORDS * 4);
        uint32_t wdst = xdst + XS_WORDS * 4;
        #pragma unroll 2
        for (int i = tid; i < XS_WORDS / 4; i += 256)
            cp16(xdst + i * 16, xsrc + i);
        #pragma unroll 2
        for (int i = tid; i < WS_WORDS / 4; i += 256)
            cp16(wdst + i * 16, wsrc + i);
        asm volatile("cp.async.commit_group;");
    };

    fill(0, 0);

    #pragma unroll 1
    for (int ch = 0; ch < 4; ++ch) {
        const int b = ch & 1;
        asm volatile("cp.async.wait_group 0;");
        __syncthreads();
        if (ch < 3) fill(ch + 1, b ^ 1);

        const unsigned long long* xs64 =
            (const unsigned long long*)(sm + b * BUF_WORDS);
        const unsigned long long* ws64 =
            (const unsigned long long*)(sm + b * BUF_WORDS + XS_WORDS);

        #pragma unroll
        for (int kh = 0; kh < 3; ++kh) {
            const int arow = hpr + kh;
            #pragma unroll
            for (int kw = 0; kw < 3; ++kw) {
                const int kk = kh * 3 + kw;
                uint32_t A[2][4];
                #pragma unroll
                for (int t = 0; t < 2; ++t) {
                    int u  = u0 + 16 * t + qv + kw;
                    int e2 = ((u >> 3) & 3) ^ ((u & 4) >> 1);
                    unsigned long long va = xs64[(arow * XP + u) * 4 + (kv ^ e2)];
                    int u2  = u + 8;
                    int e2b = ((u2 >> 3) & 3) ^ ((u2 & 4) >> 1);
                    unsigned long long vb = xs64[(arow * XP + u2) * 4 + (kv ^ e2b)];
                    A[t][0] = (uint32_t)va;
                    A[t][2] = (uint32_t)(va >> 32);
                    A[t][1] = (uint32_t)vb;
                    A[t][3] = (uint32_t)(vb >> 32);
                }
                #pragma unroll
                for (int j = 0; j < 8; ++j) {
                    unsigned long long bv = ws64[(kk * 64 + j * 8 + qv) * 4 + kv];
                    uint32_t b0 = (uint32_t)bv;
                    uint32_t b1 = (uint32_t)(bv >> 32);
                    MMA16(acc[0][j], A[0][0], A[0][1], A[0][2], A[0][3], b0, b1);
                    MMA16(acc[1][j], A[1][0], A[1][1], A[1][2], A[1][3], b0, b1);
                }
            }
        }
        __syncthreads();   // all warps done with buffer b before its refill (ch+2)
    }

    // ---- direct epilogue: fragments + bias -> global ----
    const int hh = h0 + hpr;
    #pragma unroll
    for (int t = 0; t < 2; ++t) {
        const int ub = u0 + 16 * t + qv;
        #pragma unroll
        for (int j = 0; j < 8; ++j) {
            const int f0 = j * 8 + kv * 2;
            float* o0 = out + ((size_t)(n * COUT + f0) * HH + hh) * WW;
            if (ub < WW) {
                o0[ub]      = acc[t][j][0] + bj0[j];
                o0[HW + ub] = acc[t][j][1] + bj1[j];
            }
            if (ub + 8 < WW) {
                o0[ub + 8]      = acc[t][j][2] + bj0[j];
                o0[HW + ub + 8] = acc[t][j][3] + bj1[j];
            }
        }
    }
}

extern "C" void kernel_launch(void* const* d_in, const int* in_sizes, int n_in,
                              void* d_out, int out_size) {
    const float* x    = (const float*)d_in[0];
    const float* wt   = (const float*)d_in[1];
    const float* bias = (const float*)d_in[2];
    float* out = (float*)d_out;

    cudaFuncSetAttribute(conv_mma_kernel,
                         cudaFuncAttributeMaxDynamicSharedMemorySize, SMEM_BYTES);
    prep_weights<<<(4 * WS_WORDS + 255) / 256, 256>>>(wt);
    size_t nx = (size_t)NB * 4 * XROWS * XP * 8;
    prep_x<<<(unsigned)((nx + 255) / 256), 256>>>(x);
    conv_mma_kernel<<<NB * 56, 256, SMEM_BYTES>>>(bias, out);
}

// round 7
// speedup vs baseline: 4.8815x; 1.1844x over previous
#include <cuda_runtime.h>
#include <cuda_fp16.h>
#include <cstdint>

// Conv2d 3x3 s1 p1: x(16,64,112,112) fp32, w(64,64,3,3), b(64) -> out(16,64,112,112)
//
// R7: fp16 m16n8k16 implicit GEMM, 4 output rows/CTA (512 thr, 16 warps),
// cp.async double-buffered pipeline, single merged coalesced prologue.

#define CIN  64
#define COUT 64
#define HH   112
#define WW   112
#define NB   16
#define HW   (HH*WW)

#define XP       132
#define XROWS    114
#define XS_WORDS (6 * XP * 8)           // 6336 u32 (6 padded rows)
#define WS_WORDS (9 * 64 * 8)           // 4608 u32
#define BUF_WORDS (XS_WORDS + WS_WORDS) // 10944
#define SMEM_BYTES (2 * BUF_WORDS * 4)  // 87552

// baked input: [n][chunk4][row114][u132][slot8] fp16x2, swizzle pre-applied
__device__ uint32_t g_x16[(size_t)NB * 4 * XROWS * XP * 8];
// prepped weights: [chunk4][kk9][f64][cp'8] fp16x2
__device__ uint32_t g_wt16[4 * WS_WORDS];

#define PREP_X_THREADS ((size_t)NB * 4 * XROWS * XP)        // 964224
#define PREP_X_BLOCKS  ((unsigned)((PREP_X_THREADS + 255) / 256))
#define PREP_W_BLOCKS  ((4 * WS_WORDS + 255) / 256)

__global__ void prep_all(const float* __restrict__ x,
                         const float* __restrict__ wt) {
    if (blockIdx.x >= PREP_X_BLOCKS) {
        int idx = (blockIdx.x - PREP_X_BLOCKS) * blockDim.x + threadIdx.x;
        if (idx >= 4 * WS_WORDS) return;
        int ch  = idx / WS_WORDS;
        int rem = idx % WS_WORDS;
        int kk  = rem >> 9;
        int f   = (rem >> 3) & 63;
        int cpp = rem & 7;
        int cp  = (cpp >> 1) + ((cpp & 1) << 2);
        int c0  = ch * 16 + 2 * cp;
        __half2 hv = __floats2half2_rn(wt[(f * CIN + c0) * 9 + kk],
                                       wt[(f * CIN + c0 + 1) * 9 + kk]);
        g_wt16[idx] = *(uint32_t*)&hv;
        return;
    }
    size_t idx = (size_t)blockIdx.x * blockDim.x + threadIdx.x;
    if (idx >= PREP_X_THREADS) return;
    int u    = idx % XP;                 // fastest -> coalesced x reads
    size_t t = idx / XP;
    int row  = t % XROWS;
    size_t t2 = t / XROWS;
    int ch   = t2 & 3;
    int n    = t2 >> 2;

    int gh = row - 1, gw = u - 1;
    bool ok = ((unsigned)gh < HH) && ((unsigned)gw < WW);
    const int e = ((((u >> 3) & 3) << 1) ^ (u & 4));

    uint32_t slots[8];
    #pragma unroll
    for (int cp = 0; cp < 8; ++cp) {
        uint32_t v = 0;
        if (ok) {
            const float* p = x +
                ((size_t)(n * CIN + ch * 16 + 2 * cp) * HH + gh) * WW + gw;
            __half2 hv = __floats2half2_rn(p[0], p[HW]);
            v = *(uint32_t*)&hv;
        }
        slots[((2 * (cp & 3)) | (cp >> 2)) ^ e] = v;
    }
    uint4* dst = (uint4*)(g_x16 + idx * 8);
    dst[0] = make_uint4(slots[0], slots[1], slots[2], slots[3]);
    dst[1] = make_uint4(slots[4], slots[5], slots[6], slots[7]);
}

#define MMA16(d, a0, a1, a2, a3, b0, b1)                                     \
    asm volatile("mma.sync.aligned.m16n8k16.row.col.f32.f16.f16.f32 "        \
        "{%0,%1,%2,%3}, {%4,%5,%6,%7}, {%8,%9}, {%0,%1,%2,%3};"              \
        : "+f"(d[0]), "+f"(d[1]), "+f"(d[2]), "+f"(d[3])                     \
        : "r"(a0), "r"(a1), "r"(a2), "r"(a3), "r"(b0), "r"(b1))

__device__ __forceinline__ void cp16(uint32_t dst, const void* src) {
    asm volatile("cp.async.ca.shared.global [%0], [%1], 16;"
                 :: "r"(dst), "l"(src));
}

__global__ __launch_bounds__(512, 1)
void conv_mma_kernel(const float* __restrict__ bias,
                     float* __restrict__ out) {
    extern __shared__ uint32_t sm[];
    const uint32_t sbase = (uint32_t)__cvta_generic_to_shared(sm);

    const int tid  = threadIdx.x;
    const int lane = tid & 31;
    const int wid  = tid >> 5;            // 0..15
    const int qv   = lane >> 2;
    const int kv   = lane & 3;
    const int hpr  = wid >> 2;            // 0..3 : output row within quad
    const int u0   = (wid & 3) * 32;

    const int n  = blockIdx.x / 28;
    const int h0 = (blockIdx.x % 28) * 4;

    float bj0[8], bj1[8];
    #pragma unroll
    for (int j = 0; j < 8; ++j) {
        bj0[j] = __ldg(bias + j * 8 + kv * 2);
        bj1[j] = __ldg(bias + j * 8 + kv * 2 + 1);
    }

    float acc[2][8][4];
    #pragma unroll
    for (int t = 0; t < 2; ++t)
        #pragma unroll
        for (int j = 0; j < 8; ++j)
            #pragma unroll
            for (int r = 0; r < 4; ++r) acc[t][j][r] = 0.f;

    auto fill = [&](int ch, int b) {
        const uint4* xsrc = (const uint4*)(g_x16 +
            (((size_t)(n * 4 + ch) * XROWS + h0) * (XP * 8)));
        const uint4* wsrc = (const uint4*)(g_wt16 + ch * WS_WORDS);
        uint32_t xdst = sbase + b * (BUF_WORDS * 4);
        uint32_t wdst = xdst + XS_WORDS * 4;
        #pragma unroll 2
        for (int i = tid; i < XS_WORDS / 4; i += 512)
            cp16(xdst + i * 16, xsrc + i);
        #pragma unroll 2
        for (int i = tid; i < WS_WORDS / 4; i += 512)
            cp16(wdst + i * 16, wsrc + i);
        asm volatile("cp.async.commit_group;");
    };

    fill(0, 0);

    #pragma unroll 1
    for (int ch = 0; ch < 4; ++ch) {
        const int b = ch & 1;
        asm volatile("cp.async.wait_group 0;");
        __syncthreads();
        if (ch < 3) fill(ch + 1, b ^ 1);

        const unsigned long long* xs64 =
            (const unsigned long long*)(sm + b * BUF_WORDS);
        const unsigned long long* ws64 =
            (const unsigned long long*)(sm + b * BUF_WORDS + XS_WORDS);

        #pragma unroll
        for (int kh = 0; kh < 3; ++kh) {
            const int arow = hpr + kh;        // 0..5
            #pragma unroll
            for (int kw = 0; kw < 3; ++kw) {
                const int kk = kh * 3 + kw;
                uint32_t A[2][4];
                #pragma unroll
                for (int t = 0; t < 2; ++t) {
                    int u  = u0 + 16 * t + qv + kw;
                    int e2 = ((u >> 3) & 3) ^ ((u & 4) >> 1);
                    unsigned long long va = xs64[(arow * XP + u) * 4 + (kv ^ e2)];
                    int u2  = u + 8;
                    int e2b = ((u2 >> 3) & 3) ^ ((u2 & 4) >> 1);
                    unsigned long long vb = xs64[(arow * XP + u2) * 4 + (kv ^ e2b)];
                    A[t][0] = (uint32_t)va;
                    A[t][2] = (uint32_t)(va >> 32);
                    A[t][1] = (uint32_t)vb;
                    A[t][3] = (uint32_t)(vb >> 32);
                }
                #pragma unroll
                for (int j = 0; j < 8; ++j) {
                    unsigned long long bv = ws64[(kk * 64 + j * 8 + qv) * 4 + kv];
                    uint32_t b0 = (uint32_t)bv;
                    uint32_t b1 = (uint32_t)(bv >> 32);
                    MMA16(acc[0][j], A[0][0], A[0][1], A[0][2], A[0][3], b0, b1);
                    MMA16(acc[1][j], A[1][0], A[1][1], A[1][2], A[1][3], b0, b1);
                }
            }
        }
        __syncthreads();   // all warps done with buffer b before refill (ch+2)
    }

    // ---- direct epilogue: fragments + bias -> global ----
    const int hh = h0 + hpr;
    #pragma unroll
    for (int t = 0; t < 2; ++t) {
        const int ub = u0 + 16 * t + qv;
        #pragma unroll
        for (int j = 0; j < 8; ++j) {
            const int f0 = j * 8 + kv * 2;
            float* o0 = out + ((size_t)(n * COUT + f0) * HH + hh) * WW;
            if (ub < WW) {
                o0[ub]      = acc[t][j][0] + bj0[j];
                o0[HW + ub] = acc[t][j][1] + bj1[j];
            }
            if (ub + 8 < WW) {
                o0[ub + 8]      = acc[t][j][2] + bj0[j];
                o0[HW + ub + 8] = acc[t][j][3] + bj1[j];
            }
        }
    }
}

extern "C" void kernel_launch(void* const* d_in, const int* in_sizes, int n_in,
                              void* d_out, int out_size) {
    const float* x    = (const float*)d_in[0];
    const float* wt   = (const float*)d_in[1];
    const float* bias = (const float*)d_in[2];
    float* out = (float*)d_out;

    cudaFuncSetAttribute(conv_mma_kernel,
                         cudaFuncAttributeMaxDynamicSharedMemorySize, SMEM_BYTES);
    prep_all<<<PREP_X_BLOCKS + PREP_W_BLOCKS, 256>>>(x, wt);
    conv_mma_kernel<<<NB * 28, 512, SMEM_BYTES>>>(bias, out);
}

// round 8
// speedup vs baseline: 4.9751x; 1.0192x over previous
#include <cuda_runtime.h>
#include <cuda_fp16.h>
#include <cstdint>

// Conv2d 3x3 s1 p1: x(16,64,112,112) fp32, w(64,64,3,3), b(64) -> out(16,64,112,112)
//
// R8: fp16 m16n8k16 implicit GEMM. 4 output rows/CTA, 256 threads / 8 warps,
// each warp M=64 x N=64 (B reused 4x) -> 128 B of LDS per MMA (was 192),
// cp.async double-buffered pipeline, merged coalesced prologue.

#define CIN  64
#define COUT 64
#define HH   112
#define WW   112
#define NB   16
#define HW   (HH*WW)

#define XP       132
#define XROWS    114
#define XS_WORDS (6 * XP * 8)           // 6336 u32 (6 padded rows)
#define WS_WORDS (9 * 64 * 8)           // 4608 u32
#define BUF_WORDS (XS_WORDS + WS_WORDS) // 10944
#define SMEM_BYTES (2 * BUF_WORDS * 4)  // 87552

// baked input: [n][chunk4][row114][u132][slot8] fp16x2, swizzle pre-applied
__device__ uint32_t g_x16[(size_t)NB * 4 * XROWS * XP * 8];
// prepped weights: [chunk4][kk9][f64][cp'8] fp16x2
__device__ uint32_t g_wt16[4 * WS_WORDS];

#define PREP_X_THREADS ((size_t)NB * 4 * XROWS * XP)        // 964224
#define PREP_X_BLOCKS  ((unsigned)((PREP_X_THREADS + 255) / 256))
#define PREP_W_BLOCKS  ((4 * WS_WORDS + 255) / 256)

__global__ void prep_all(const float* __restrict__ x,
                         const float* __restrict__ wt) {
    if (blockIdx.x >= PREP_X_BLOCKS) {
        int idx = (blockIdx.x - PREP_X_BLOCKS) * blockDim.x + threadIdx.x;
        if (idx >= 4 * WS_WORDS) return;
        int ch  = idx / WS_WORDS;
        int rem = idx % WS_WORDS;
        int kk  = rem >> 9;
        int f   = (rem >> 3) & 63;
        int cpp = rem & 7;
        int cp  = (cpp >> 1) + ((cpp & 1) << 2);
        int c0  = ch * 16 + 2 * cp;
        __half2 hv = __floats2half2_rn(wt[(f * CIN + c0) * 9 + kk],
                                       wt[(f * CIN + c0 + 1) * 9 + kk]);
        g_wt16[idx] = *(uint32_t*)&hv;
        return;
    }
    size_t idx = (size_t)blockIdx.x * blockDim.x + threadIdx.x;
    if (idx >= PREP_X_THREADS) return;
    int u    = idx % XP;                 // fastest -> coalesced x reads
    size_t t = idx / XP;
    int row  = t % XROWS;
    size_t t2 = t / XROWS;
    int ch   = t2 & 3;
    int n    = t2 >> 2;

    int gh = row - 1, gw = u - 1;
    bool ok = ((unsigned)gh < HH) && ((unsigned)gw < WW);
    const int e = ((((u >> 3) & 3) << 1) ^ (u & 4));

    uint32_t slots[8];
    #pragma unroll
    for (int cp = 0; cp < 8; ++cp) {
        uint32_t v = 0;
        if (ok) {
            const float* p = x +
                ((size_t)(n * CIN + ch * 16 + 2 * cp) * HH + gh) * WW + gw;
            __half2 hv = __floats2half2_rn(p[0], p[HW]);
            v = *(uint32_t*)&hv;
        }
        slots[((2 * (cp & 3)) | (cp >> 2)) ^ e] = v;
    }
    uint4* dst = (uint4*)(g_x16 + idx * 8);
    dst[0] = make_uint4(slots[0], slots[1], slots[2], slots[3]);
    dst[1] = make_uint4(slots[4], slots[5], slots[6], slots[7]);
}

#define MMA16(d, a0, a1, a2, a3, b0, b1)                                     \
    asm volatile("mma.sync.aligned.m16n8k16.row.col.f32.f16.f16.f32 "        \
        "{%0,%1,%2,%3}, {%4,%5,%6,%7}, {%8,%9}, {%0,%1,%2,%3};"              \
        : "+f"(d[0]), "+f"(d[1]), "+f"(d[2]), "+f"(d[3])                     \
        : "r"(a0), "r"(a1), "r"(a2), "r"(a3), "r"(b0), "r"(b1))

__device__ __forceinline__ void cp16(uint32_t dst, const void* src) {
    asm volatile("cp.async.ca.shared.global [%0], [%1], 16;"
                 :: "r"(dst), "l"(src));
}

__global__ __launch_bounds__(256, 1)
void conv_mma_kernel(const float* __restrict__ bias,
                     float* __restrict__ out) {
    extern __shared__ uint32_t sm[];
    const uint32_t sbase = (uint32_t)__cvta_generic_to_shared(sm);

    const int tid  = threadIdx.x;
    const int lane = tid & 31;
    const int wid  = tid >> 5;            // 0..7
    const int qv   = lane >> 2;
    const int kv   = lane & 3;
    const int hpr  = wid >> 1;            // 0..3 : output row within quad
    const int u0   = (wid & 1) * 64;      // u-half

    const int n  = blockIdx.x / 28;
    const int h0 = (blockIdx.x % 28) * 4;

    float acc[4][8][4];
    #pragma unroll
    for (int t = 0; t < 4; ++t)
        #pragma unroll
        for (int j = 0; j < 8; ++j)
            #pragma unroll
            for (int r = 0; r < 4; ++r) acc[t][j][r] = 0.f;

    auto fill = [&](int ch, int b) {
        const uint4* xsrc = (const uint4*)(g_x16 +
            (((size_t)(n * 4 + ch) * XROWS + h0) * (XP * 8)));
        const uint4* wsrc = (const uint4*)(g_wt16 + ch * WS_WORDS);
        uint32_t xdst = sbase + b * (BUF_WORDS * 4);
        uint32_t wdst = xdst + XS_WORDS * 4;
        #pragma unroll 2
        for (int i = tid; i < XS_WORDS / 4; i += 256)
            cp16(xdst + i * 16, xsrc + i);
        #pragma unroll 2
        for (int i = tid; i < WS_WORDS / 4; i += 256)
            cp16(wdst + i * 16, wsrc + i);
        asm volatile("cp.async.commit_group;");
    };

    fill(0, 0);

    #pragma unroll 1
    for (int ch = 0; ch < 4; ++ch) {
        const int b = ch & 1;
        asm volatile("cp.async.wait_group 0;");
        __syncthreads();
        if (ch < 3) fill(ch + 1, b ^ 1);

        const unsigned long long* xs64 =
            (const unsigned long long*)(sm + b * BUF_WORDS);
        const unsigned long long* ws64 =
            (const unsigned long long*)(sm + b * BUF_WORDS + XS_WORDS);

        #pragma unroll
        for (int kh = 0; kh < 3; ++kh) {
            const int arow = hpr + kh;        // 0..5
            #pragma unroll
            for (int kw = 0; kw < 3; ++kw) {
                const int kk = kh * 3 + kw;
                uint32_t A[4][4];
                #pragma unroll
                for (int t = 0; t < 4; ++t) {
                    int u  = u0 + 16 * t + qv + kw;
                    int e2 = ((u >> 3) & 3) ^ ((u & 4) >> 1);
                    unsigned long long va = xs64[(arow * XP + u) * 4 + (kv ^ e2)];
                    int u2  = u + 8;
                    int e2b = ((u2 >> 3) & 3) ^ ((u2 & 4) >> 1);
                    unsigned long long vb = xs64[(arow * XP + u2) * 4 + (kv ^ e2b)];
                    A[t][0] = (uint32_t)va;
                    A[t][2] = (uint32_t)(va >> 32);
                    A[t][1] = (uint32_t)vb;
                    A[t][3] = (uint32_t)(vb >> 32);
                }
                #pragma unroll
                for (int j = 0; j < 8; ++j) {
                    unsigned long long bv = ws64[(kk * 64 + j * 8 + qv) * 4 + kv];
                    uint32_t b0 = (uint32_t)bv;
                    uint32_t b1 = (uint32_t)(bv >> 32);
                    MMA16(acc[0][j], A[0][0], A[0][1], A[0][2], A[0][3], b0, b1);
                    MMA16(acc[1][j], A[1][0], A[1][1], A[1][2], A[1][3], b0, b1);
                    MMA16(acc[2][j], A[2][0], A[2][1], A[2][2], A[2][3], b0, b1);
                    MMA16(acc[3][j], A[3][0], A[3][1], A[3][2], A[3][3], b0, b1);
                }
            }
        }
        __syncthreads();   // all warps done with buffer b before refill (ch+2)
    }

    // ---- direct epilogue: fragments + bias -> global ----
    float bj0[8], bj1[8];
    #pragma unroll
    for (int j = 0; j < 8; ++j) {
        bj0[j] = __ldg(bias + j * 8 + kv * 2);
        bj1[j] = __ldg(bias + j * 8 + kv * 2 + 1);
    }
    const int hh = h0 + hpr;
    #pragma unroll
    for (int t = 0; t < 4; ++t) {
        const int ub = u0 + 16 * t + qv;
        #pragma unroll
        for (int j = 0; j < 8; ++j) {
            const int f0 = j * 8 + kv * 2;
            float* o0 = out + ((size_t)(n * COUT + f0) * HH + hh) * WW;
            if (ub < WW) {
                o0[ub]      = acc[t][j][0] + bj0[j];
                o0[HW + ub] = acc[t][j][1] + bj1[j];
            }
            if (ub + 8 < WW) {
                o0[ub + 8]      = acc[t][j][2] + bj0[j];
                o0[HW + ub + 8] = acc[t][j][3] + bj1[j];
            }
        }
    }
}

extern "C" void kernel_launch(void* const* d_in, const int* in_sizes, int n_in,
                              void* d_out, int out_size) {
    const float* x    = (const float*)d_in[0];
    const float* wt   = (const float*)d_in[1];
    const float* bias = (const float*)d_in[2];
    float* out = (float*)d_out;

    cudaFuncSetAttribute(conv_mma_kernel,
                         cudaFuncAttributeMaxDynamicSharedMemorySize, SMEM_BYTES);
    prep_all<<<PREP_X_BLOCKS + PREP_W_BLOCKS, 256>>>(x, wt);
    conv_mma_kernel<<<NB * 28, 256, SMEM_BYTES>>>(bias, out);
}

// round 9
// speedup vs baseline: 5.0590x; 1.0169x over previous
#include <cuda_runtime.h>
#include <cuda_fp16.h>
#include <cstdint>

// Conv2d 3x3 s1 p1: x(16,64,112,112) fp32, w(64,64,3,3), b(64) -> out(16,64,112,112)
//
// R9: fp16 m16n8k16 implicit GEMM. 2 output rows/CTA, 128 threads / 4 warps,
// each warp M=64 x N=64. Small CTA => 2 CTAs/SM: barrier/fill exposure hidden
// by the co-resident CTA, and the tail wave shrinks to 8 half-size CTAs.

#define CIN  64
#define COUT 64
#define HH   112
#define WW   112
#define NB   16
#define HW   (HH*WW)

#define XP       132
#define XROWS    114
#define XS_WORDS (4 * XP * 8)           // 4224 u32 (4 padded rows)
#define WS_WORDS (9 * 64 * 8)           // 4608 u32
#define BUF_WORDS (XS_WORDS + WS_WORDS) // 8832
#define SMEM_BYTES (2 * BUF_WORDS * 4)  // 70656

// baked input: [n][chunk4][row114][u132][slot8] fp16x2, swizzle pre-applied
__device__ uint32_t g_x16[(size_t)NB * 4 * XROWS * XP * 8];
// prepped weights: [chunk4][kk9][f64][cp'8] fp16x2
__device__ uint32_t g_wt16[4 * WS_WORDS];

#define PREP_X_THREADS ((size_t)NB * 4 * XROWS * XP)        // 964224
#define PREP_X_BLOCKS  ((unsigned)((PREP_X_THREADS + 255) / 256))
#define PREP_W_BLOCKS  ((4 * WS_WORDS + 255) / 256)

__global__ void prep_all(const float* __restrict__ x,
                         const float* __restrict__ wt) {
    if (blockIdx.x >= PREP_X_BLOCKS) {
        int idx = (blockIdx.x - PREP_X_BLOCKS) * blockDim.x + threadIdx.x;
        if (idx >= 4 * WS_WORDS) return;
        int ch  = idx / WS_WORDS;
        int rem = idx % WS_WORDS;
        int kk  = rem >> 9;
        int f   = (rem >> 3) & 63;
        int cpp = rem & 7;
        int cp  = (cpp >> 1) + ((cpp & 1) << 2);
        int c0  = ch * 16 + 2 * cp;
        __half2 hv = __floats2half2_rn(wt[(f * CIN + c0) * 9 + kk],
                                       wt[(f * CIN + c0 + 1) * 9 + kk]);
        g_wt16[idx] = *(uint32_t*)&hv;
        return;
    }
    size_t idx = (size_t)blockIdx.x * blockDim.x + threadIdx.x;
    if (idx >= PREP_X_THREADS) return;
    int u    = idx % XP;                 // fastest -> coalesced x reads
    size_t t = idx / XP;
    int row  = t % XROWS;
    size_t t2 = t / XROWS;
    int ch   = t2 & 3;
    int n    = t2 >> 2;

    int gh = row - 1, gw = u - 1;
    bool ok = ((unsigned)gh < HH) && ((unsigned)gw < WW);
    const int e = ((((u >> 3) & 3) << 1) ^ (u & 4));

    uint32_t slots[8];
    #pragma unroll
    for (int cp = 0; cp < 8; ++cp) {
        uint32_t v = 0;
        if (ok) {
            const float* p = x +
                ((size_t)(n * CIN + ch * 16 + 2 * cp) * HH + gh) * WW + gw;
            __half2 hv = __floats2half2_rn(p[0], p[HW]);
            v = *(uint32_t*)&hv;
        }
        slots[((2 * (cp & 3)) | (cp >> 2)) ^ e] = v;
    }
    uint4* dst = (uint4*)(g_x16 + idx * 8);
    dst[0] = make_uint4(slots[0], slots[1], slots[2], slots[3]);
    dst[1] = make_uint4(slots[4], slots[5], slots[6], slots[7]);
}

#define MMA16(d, a0, a1, a2, a3, b0, b1)                                     \
    asm volatile("mma.sync.aligned.m16n8k16.row.col.f32.f16.f16.f32 "        \
        "{%0,%1,%2,%3}, {%4,%5,%6,%7}, {%8,%9}, {%0,%1,%2,%3};"              \
        : "+f"(d[0]), "+f"(d[1]), "+f"(d[2]), "+f"(d[3])                     \
        : "r"(a0), "r"(a1), "r"(a2), "r"(a3), "r"(b0), "r"(b1))

__device__ __forceinline__ void cp16(uint32_t dst, const void* src) {
    asm volatile("cp.async.ca.shared.global [%0], [%1], 16;"
                 :: "r"(dst), "l"(src));
}

__global__ __launch_bounds__(128, 2)
void conv_mma_kernel(const float* __restrict__ bias,
                     float* __restrict__ out) {
    extern __shared__ uint32_t sm[];
    const uint32_t sbase = (uint32_t)__cvta_generic_to_shared(sm);

    const int tid  = threadIdx.x;
    const int lane = tid & 31;
    const int wid  = tid >> 5;            // 0..3
    const int qv   = lane >> 2;
    const int kv   = lane & 3;
    const int hpr  = wid >> 1;            // 0..1 : output row within pair
    const int u0   = (wid & 1) * 64;      // u-half

    const int n  = blockIdx.x / 56;
    const int h0 = (blockIdx.x % 56) * 2;

    float acc[4][8][4];
    #pragma unroll
    for (int t = 0; t < 4; ++t)
        #pragma unroll
        for (int j = 0; j < 8; ++j)
            #pragma unroll
            for (int r = 0; r < 4; ++r) acc[t][j][r] = 0.f;

    auto fill = [&](int ch, int b) {
        const uint4* xsrc = (const uint4*)(g_x16 +
            (((size_t)(n * 4 + ch) * XROWS + h0) * (XP * 8)));
        const uint4* wsrc = (const uint4*)(g_wt16 + ch * WS_WORDS);
        uint32_t xdst = sbase + b * (BUF_WORDS * 4);
        uint32_t wdst = xdst + XS_WORDS * 4;
        #pragma unroll 2
        for (int i = tid; i < XS_WORDS / 4; i += 128)
            cp16(xdst + i * 16, xsrc + i);
        #pragma unroll 2
        for (int i = tid; i < WS_WORDS / 4; i += 128)
            cp16(wdst + i * 16, wsrc + i);
        asm volatile("cp.async.commit_group;");
    };

    fill(0, 0);

    #pragma unroll 1
    for (int ch = 0; ch < 4; ++ch) {
        const int b = ch & 1;
        asm volatile("cp.async.wait_group 0;");
        __syncthreads();
        if (ch < 3) fill(ch + 1, b ^ 1);

        const unsigned long long* xs64 =
            (const unsigned long long*)(sm + b * BUF_WORDS);
        const unsigned long long* ws64 =
            (const unsigned long long*)(sm + b * BUF_WORDS + XS_WORDS);

        #pragma unroll
        for (int kh = 0; kh < 3; ++kh) {
            const int arow = hpr + kh;        // 0..3
            #pragma unroll
            for (int kw = 0; kw < 3; ++kw) {
                const int kk = kh * 3 + kw;
                uint32_t A[4][4];
                #pragma unroll
                for (int t = 0; t < 4; ++t) {
                    int u  = u0 + 16 * t + qv + kw;
                    int e2 = ((u >> 3) & 3) ^ ((u & 4) >> 1);
                    unsigned long long va = xs64[(arow * XP + u) * 4 + (kv ^ e2)];
                    int u2  = u + 8;
                    int e2b = ((u2 >> 3) & 3) ^ ((u2 & 4) >> 1);
                    unsigned long long vb = xs64[(arow * XP + u2) * 4 + (kv ^ e2b)];
                    A[t][0] = (uint32_t)va;
                    A[t][2] = (uint32_t)(va >> 32);
                    A[t][1] = (uint32_t)vb;
                    A[t][3] = (uint32_t)(vb >> 32);
                }
                #pragma unroll
                for (int j = 0; j < 8; ++j) {
                    unsigned long long bv = ws64[(kk * 64 + j * 8 + qv) * 4 + kv];
                    uint32_t b0 = (uint32_t)bv;
                    uint32_t b1 = (uint32_t)(bv >> 32);
                    MMA16(acc[0][j], A[0][0], A[0][1], A[0][2], A[0][3], b0, b1);
                    MMA16(acc[1][j], A[1][0], A[1][1], A[1][2], A[1][3], b0, b1);
                    MMA16(acc[2][j], A[2][0], A[2][1], A[2][2], A[2][3], b0, b1);
                    MMA16(acc[3][j], A[3][0], A[3][1], A[3][2], A[3][3], b0, b1);
                }
            }
        }
        __syncthreads();   // all warps done with buffer b before refill (ch+2)
    }

    // ---- direct epilogue: fragments + bias -> global ----
    float bj0[8], bj1[8];
    #pragma unroll
    for (int j = 0; j < 8; ++j) {
        bj0[j] = __ldg(bias + j * 8 + kv * 2);
        bj1[j] = __ldg(bias + j * 8 + kv * 2 + 1);
    }
    const int hh = h0 + hpr;
    #pragma unroll
    for (int t = 0; t < 4; ++t) {
        const int ub = u0 + 16 * t + qv;
        #pragma unroll
        for (int j = 0; j < 8; ++j) {
            const int f0 = j * 8 + kv * 2;
            float* o0 = out + ((size_t)(n * COUT + f0) * HH + hh) * WW;
            if (ub < WW) {
                o0[ub]      = acc[t][j][0] + bj0[j];
                o0[HW + ub] = acc[t][j][1] + bj1[j];
            }
            if (ub + 8 < WW) {
                o0[ub + 8]      = acc[t][j][2] + bj0[j];
                o0[HW + ub + 8] = acc[t][j][3] + bj1[j];
            }
        }
    }
}

extern "C" void kernel_launch(void* const* d_in, const int* in_sizes, int n_in,
                              void* d_out, int out_size) {
    const float* x    = (const float*)d_in[0];
    const float* wt   = (const float*)d_in[1];
    const float* bias = (const float*)d_in[2];
    float* out = (float*)d_out;

    cudaFuncSetAttribute(conv_mma_kernel,
                         cudaFuncAttributeMaxDynamicSharedMemorySize, SMEM_BYTES);
    prep_all<<<PREP_X_BLOCKS + PREP_W_BLOCKS, 256>>>(x, wt);
    conv_mma_kernel<<<NB * 56, 128, SMEM_BYTES>>>(bias, out);
}